// round 10
// baseline (speedup 1.0000x reference)
#include <cuda_runtime.h>
#include <cuda_bf16.h>
#include <stdint.h>

#define C_DIM 256
#define HW    4096
#define HWF   65536

// ------------------------------ scratch (EXACT set from the R7 kernel that passed)
__device__ float g_q[(size_t)2 * C_DIM * HW];       // 8.4 MB
__device__ float g_k[(size_t)2 * C_DIM * HWF];      // 134 MB
__device__ float g_v[(size_t)2 * C_DIM * HWF];      // 134 MB

// ------------------------------ helpers
__device__ __forceinline__ uint32_t smem_u32(const void* p) {
    return (uint32_t)__cvta_generic_to_shared(p);
}
__device__ __forceinline__ void cp16(uint32_t s, const void* g) {
    asm volatile("cp.async.cg.shared.global [%0], [%1], 16;\n" :: "r"(s), "l"(g) : "memory");
}
#define CP_COMMIT() asm volatile("cp.async.commit_group;\n" ::: "memory")
#define CP_WAIT1()  asm volatile("cp.async.wait_group 1;\n" ::: "memory")
#define CP_WAIT0()  asm volatile("cp.async.wait_group 0;\n" ::: "memory")

__device__ __forceinline__ void mma16816(float* d, const uint32_t* a, const uint32_t* b) {
    asm volatile(
        "mma.sync.aligned.m16n8k16.row.col.f32.bf16.bf16.f32 "
        "{%0,%1,%2,%3}, {%4,%5,%6,%7}, {%8,%9}, {%0,%1,%2,%3};"
        : "+f"(d[0]), "+f"(d[1]), "+f"(d[2]), "+f"(d[3])
        : "r"(a[0]), "r"(a[1]), "r"(a[2]), "r"(a[3]), "r"(b[0]), "r"(b[1]));
}

// split float pair -> bf16x2 hi (rounded) + bf16x2 lo (residual); f0 in low half
__device__ __forceinline__ void split2(float f0, float f1, uint32_t& hi, uint32_t& lo) {
    __nv_bfloat162 h2 = __float22bfloat162_rn(make_float2(f0, f1));
    float2 hf = __bfloat1622float2(h2);
    __nv_bfloat162 l2 = __float22bfloat162_rn(make_float2(f0 - hf.x, f1 - hf.y));
    hi = *reinterpret_cast<uint32_t*>(&h2);
    lo = *reinterpret_cast<uint32_t*>(&l2);
}

// ------------------------------ warp-MMA GEMM (R7 structure + CTA-wide B convert)
// Out[bb][ot*128+m][jt*128+n] = (sum_c W[m][c] * F[bb][c][n] + bias[m]) * scale
// CTA 128x128, K-chunks of 32, 8 warps (4m x 2n), warp tile 32x64.
// Per-stage SMEM (57344 B):
//   +0      A fp32 [128m][40 words]   (as in R7; A split stays in-register)
//   +20480  Bst fp32 [32k][128 words] (cp.async staging)
//   +36864  Bcv hi  [128n][80B]       (bf16 k-pair uint32, 16 pairs/row)
//   +47104  Bcv lo  [128n][80B]
#define AS_STRIDE 40
#define BST_OFF  20480
#define BCV_OFF  36864
#define BCV_TILE 10240
#define STG_BYTES 57344
#define SMEM_TOT (2 * STG_BYTES)     // 114688

__global__ __launch_bounds__(256, 1)
void gemm_mma(const float* __restrict__ W, const float* __restrict__ F,
              const float* __restrict__ bias, float* __restrict__ Out,
              int J, float scale) {
    extern __shared__ char smem[];
    const int t = threadIdx.x, lane = t & 31;
    const int wid = t >> 5, wm = wid & 3, wn = wid >> 2;
    const int jt = blockIdx.x, ot = blockIdx.y, bb = blockIdx.z;
    const uint32_t sb = smem_u32(smem);

    const float* gW = W + (size_t)(ot * 128) * C_DIM;
    const float* gF = F + (size_t)bb * C_DIM * J + (size_t)jt * 128;

    // convert-phase coordinates (rotation cg makes smem writes conflict-free)
    const int cn = t & 127, chf = t >> 7, cg = (t & 127) >> 3;

    float acc[2][8][4];
#pragma unroll
    for (int mt = 0; mt < 2; mt++)
#pragma unroll
        for (int np = 0; np < 8; np++)
#pragma unroll
            for (int r = 0; r < 4; r++) acc[mt][np][r] = 0.f;

#pragma unroll 1
    for (int i = 0; i < 9; i++) {
        // ---- issue async fp32 loads for k-chunk i (i = 0..7)
        if (i < 8) {
            const uint32_t s0 = sb + (uint32_t)((i & 1) * STG_BYTES);
            // A: 1024 chunks of 16B: row m = ch>>3 (0..127), c = ch&7  (as R7)
#pragma unroll
            for (int j = 0; j < 4; j++) {
                int ch = t + 256 * j;
                int am = ch >> 3, ac = ch & 7;
                cp16(s0 + (uint32_t)(am * (AS_STRIDE * 4) + ac * 16),
                     gW + (size_t)am * C_DIM + i * 32 + ac * 4);
                // B: 1024 chunks: row k = ch>>5 (0..31), c = ch&31
                int bk = ch >> 5, bc = ch & 31;
                cp16(s0 + (uint32_t)(BST_OFF + bk * 512 + bc * 16),
                     gF + (size_t)(i * 32 + bk) * J + bc * 4);
            }
            CP_COMMIT();
        }
        if (i == 0) continue;
        if (i < 8) { CP_WAIT1(); } else { CP_WAIT0(); }
        __syncthreads();

        char* st = smem + ((i - 1) & 1) * STG_BYTES;

        // ---- convert B fp32 -> bf16 hi/lo pair layout, once per CTA
        {
            const float* bst = (const float*)(st + BST_OFF);
            char* cvh = st + BCV_OFF;
            char* cvl = cvh + BCV_TILE;
#pragma unroll
            for (int i2 = 0; i2 < 8; i2++) {
                int kp = chf * 8 + ((i2 + cg) & 7);   // k-pair 0..15
                float f0 = bst[kp * 256 + cn];        // row 2*kp
                float f1 = bst[kp * 256 + 128 + cn];  // row 2*kp+1
                uint32_t hi, lo;
                split2(f0, f1, hi, lo);
                *(uint32_t*)(cvh + cn * 80 + kp * 4) = hi;
                *(uint32_t*)(cvl + cn * 80 + kp * 4) = lo;
            }
        }
        __syncthreads();

        // ---- MMA phase: A split in-register (as R7), B pure LDS32
        {
            const float* As = (const float*)st;
            const char* cvh = st + BCV_OFF;
            const char* cvl = cvh + BCV_TILE;
#pragma unroll
            for (int ks = 0; ks < 2; ks++) {
                const int k0 = ks * 16 + (lane & 3) * 2;
                uint32_t ahi[2][4], alo[2][4];
#pragma unroll
                for (int mt = 0; mt < 2; mt++) {
                    const int r0 = wm * 32 + mt * 16 + (lane >> 2);
                    float2 f00 = *(const float2*)&As[r0 * AS_STRIDE + k0];
                    float2 f10 = *(const float2*)&As[(r0 + 8) * AS_STRIDE + k0];
                    float2 f01 = *(const float2*)&As[r0 * AS_STRIDE + k0 + 8];
                    float2 f11 = *(const float2*)&As[(r0 + 8) * AS_STRIDE + k0 + 8];
                    split2(f00.x, f00.y, ahi[mt][0], alo[mt][0]);
                    split2(f10.x, f10.y, ahi[mt][1], alo[mt][1]);
                    split2(f01.x, f01.y, ahi[mt][2], alo[mt][2]);
                    split2(f11.x, f11.y, ahi[mt][3], alo[mt][3]);
                }
#pragma unroll
                for (int np = 0; np < 8; np++) {
                    const int n = wn * 64 + np * 8 + (lane >> 2);
                    const int off = n * 80 + (ks * 8 + (lane & 3)) * 4;
                    uint32_t bh[2], bl[2];
                    bh[0] = *(const uint32_t*)(cvh + off);
                    bh[1] = *(const uint32_t*)(cvh + off + 16);
                    bl[0] = *(const uint32_t*)(cvl + off);
                    bl[1] = *(const uint32_t*)(cvl + off + 16);
#pragma unroll
                    for (int mt = 0; mt < 2; mt++) {
                        mma16816(acc[mt][np], ahi[mt], bh);   // Ahi*Bhi
                        mma16816(acc[mt][np], ahi[mt], bl);   // Ahi*Blo
                        mma16816(acc[mt][np], alo[mt], bh);   // Alo*Bhi
                    }
                }
            }
        }
        __syncthreads();
    }

    // ---- epilogue: (acc + bias) * scale   (identical to R7)
#pragma unroll
    for (int mt = 0; mt < 2; mt++)
#pragma unroll
        for (int half = 0; half < 2; half++) {
            int o = ot * 128 + wm * 32 + mt * 16 + half * 8 + (lane >> 2);
            float bi = bias[o];
            float* orow = Out + ((size_t)bb * C_DIM + o) * J
                        + (size_t)jt * 128 + wn * 64 + (lane & 3) * 2;
#pragma unroll
            for (int np = 0; np < 8; np++) {
                float2 v;
                v.x = (acc[mt][np][half * 2 + 0] + bi) * scale;
                v.y = (acc[mt][np][half * 2 + 1] + bi) * scale;
                *(float2*)(orow + np * 8) = v;
            }
        }
}

// ------------------------------ attention (identical to R7; DRAM/latency-bound)
__global__ __launch_bounds__(256)
void attn_kernel(const float* __restrict__ q, const float* __restrict__ k,
                 const float* __restrict__ v, float* __restrict__ out) {
    int t = blockIdx.x * blockDim.x + threadIdx.x;
    int x = t & 63;
    int y = (t >> 6) & 63;
    int head = (t >> 12) & 7;
    int b = t >> 15;

    const size_t chq = (size_t)(b * C_DIM + head * 32);
    const float* qb = q + chq * HW + y * 64 + x;
    const size_t fbase = chq * HWF + (size_t)(4 * y) * 256 + 4 * x;
    const float* kb = k + fbase;
    const float* vb = v + fbase;

    float logit[16];
#pragma unroll
    for (int p = 0; p < 16; p++) logit[p] = 0.f;

#pragma unroll 4
    for (int d = 0; d < 32; d++) {
        float qd = qb[(size_t)d * HW];
#pragma unroll
        for (int dy = 0; dy < 4; dy++) {
            float4 kv = *(const float4*)(kb + (size_t)d * HWF + dy * 256);
            logit[dy * 4 + 0] = fmaf(qd, kv.x, logit[dy * 4 + 0]);
            logit[dy * 4 + 1] = fmaf(qd, kv.y, logit[dy * 4 + 1]);
            logit[dy * 4 + 2] = fmaf(qd, kv.z, logit[dy * 4 + 2]);
            logit[dy * 4 + 3] = fmaf(qd, kv.w, logit[dy * 4 + 3]);
        }
    }

    float m = logit[0];
#pragma unroll
    for (int p = 1; p < 16; p++) m = fmaxf(m, logit[p]);
    float s = 0.f;
#pragma unroll
    for (int p = 0; p < 16; p++) { logit[p] = __expf(logit[p] - m); s += logit[p]; }
    float inv = 1.f / s;
#pragma unroll
    for (int p = 0; p < 16; p++) logit[p] *= inv;

    float* ob = out + chq * HW + y * 64 + x;
#pragma unroll 4
    for (int d = 0; d < 32; d++) {
        float sum = 0.f;
#pragma unroll
        for (int dy = 0; dy < 4; dy++) {
            float4 vv = *(const float4*)(vb + (size_t)d * HWF + dy * 256);
            sum = fmaf(logit[dy * 4 + 0], vv.x, sum);
            sum = fmaf(logit[dy * 4 + 1], vv.y, sum);
            sum = fmaf(logit[dy * 4 + 2], vv.z, sum);
            sum = fmaf(logit[dy * 4 + 3], vv.w, sum);
        }
        ob[(size_t)d * HW] = sum;
    }
}

// ------------------------------ launch (identical shape to R7)
extern "C" void kernel_launch(void* const* d_in, const int* in_sizes, int n_in,
                              void* d_out, int out_size) {
    const float* x  = (const float*)d_in[0];
    const float* fm = (const float*)d_in[1];
    const float* Wq = (const float*)d_in[2];
    const float* bq = (const float*)d_in[3];
    const float* Wk = (const float*)d_in[4];
    const float* bk = (const float*)d_in[5];
    const float* Wv = (const float*)d_in[6];
    const float* bv = (const float*)d_in[7];
    float* out = (float*)d_out;

    float *q, *k, *v;
    cudaGetSymbolAddress((void**)&q, g_q);
    cudaGetSymbolAddress((void**)&k, g_k);
    cudaGetSymbolAddress((void**)&v, g_v);

    cudaFuncSetAttribute(gemm_mma, cudaFuncAttributeMaxDynamicSharedMemorySize, SMEM_TOT);

    const float scaling = 0.17677669529663687f;  // 32^-0.5

    gemm_mma<<<dim3(HW / 128, 2, 2), 256, SMEM_TOT>>>(Wq, x, bq, q, HW, scaling);
    gemm_mma<<<dim3(HWF / 128, 2, 2), 256, SMEM_TOT>>>(Wk, fm, bk, k, HWF, 1.0f);
    gemm_mma<<<dim3(HWF / 128, 2, 2), 256, SMEM_TOT>>>(Wv, fm, bv, v, HWF, 1.0f);

    attn_kernel<<<(2 * 8 * HW) / 256, 256>>>(q, k, v, out);
}

// round 12
// speedup vs baseline: 1.0427x; 1.0427x over previous
#include <cuda_runtime.h>
#include <cuda_bf16.h>
#include <stdint.h>

#define C_DIM 256
#define HW    4096
#define HWF   65536

// ------------------------------ scratch (proven-passing set)
__device__ float g_q[(size_t)2 * C_DIM * HW];
__device__ float g_k[(size_t)2 * C_DIM * HWF];
__device__ float g_v[(size_t)2 * C_DIM * HWF];

// ------------------------------ helpers
__device__ __forceinline__ void mma16816(float* d, const uint32_t* a, const uint32_t* b) {
    asm volatile(
        "mma.sync.aligned.m16n8k16.row.col.f32.bf16.bf16.f32 "
        "{%0,%1,%2,%3}, {%4,%5,%6,%7}, {%8,%9}, {%0,%1,%2,%3};"
        : "+f"(d[0]), "+f"(d[1]), "+f"(d[2]), "+f"(d[3])
        : "r"(a[0]), "r"(a[1]), "r"(a[2]), "r"(a[3]), "r"(b[0]), "r"(b[1]));
}

// split float pair -> bf16x2 hi (rounded) + bf16x2 lo (residual); f0 in low half
__device__ __forceinline__ void split2(float f0, float f1, uint32_t& hi, uint32_t& lo) {
    __nv_bfloat162 h2 = __float22bfloat162_rn(make_float2(f0, f1));
    float2 hf = __bfloat1622float2(h2);
    __nv_bfloat162 l2 = __float22bfloat162_rn(make_float2(f0 - hf.x, f1 - hf.y));
    hi = *reinterpret_cast<uint32_t*>(&h2);
    lo = *reinterpret_cast<uint32_t*>(&l2);
}

// ------------------------------ warp-MMA GEMM, register-prefetch + bf16 smem tiles
// Out[bb][ot*128+m][jt*128+n] = (sum_c W[m][c] * F[bb][c][n] + bias[m]) * scale
// 512 threads, 16 warps (4m x 4n), warp tile 32x32, CTA tile 128x128, k-chunk 32.
// Per k-chunk: global fp32 prefetched into registers (hidden behind MMA phase),
// split to bf16 hi/lo in-register, stored to smem pair-layout tiles; MMA phase
// is pure LDS32 + HMMA. One __syncthreads per chunk; ping-pong stages.
// Per-stage SMEM (37888 B):
//   +0      Acv hi [128m][20 words]  (16 k-pair uint32 + 4 pad)
//   +10240  Acv lo [128m][20 words]
//   +20480  Bcv hi [16kp][136 words] (128 n + 8 pad)
//   +29184  Bcv lo [16kp][136 words]
#define ACV_LO   10240
#define BCV_HI   20480
#define BCV_LO   29184
#define STG_BYTES 37888
#define SMEM_TOT (2 * STG_BYTES)    // 75776

__global__ __launch_bounds__(512, 1)
void gemm_mma(const float* __restrict__ W, const float* __restrict__ F,
              const float* __restrict__ bias, float* __restrict__ Out,
              int J, float scale) {
    extern __shared__ char smem[];
    const int t = threadIdx.x, lane = t & 31;
    const int wid = t >> 5, wm = wid & 3, wn = wid >> 2;
    const int jt = blockIdx.x, ot = blockIdx.y, bb = blockIdx.z;

    // prefetch coordinates
    const int ra = t >> 2, qa = t & 3;         // A: row 0..127, k-segment of 8
    const int pk = t >> 5, n0 = (t & 31) * 4;  // B: k-pair row 0..15, 4 n-cols
    const float* gA = W + (size_t)(ot * 128 + ra) * C_DIM + qa * 8;
    const float* gB = F + (size_t)bb * C_DIM * J + (size_t)(2 * pk) * J
                    + (size_t)jt * 128 + n0;

    float acc[2][4][4];
#pragma unroll
    for (int mt = 0; mt < 2; mt++)
#pragma unroll
        for (int np = 0; np < 4; np++)
#pragma unroll
            for (int r = 0; r < 4; r++) acc[mt][np][r] = 0.f;

    float4 pa0, pa1, pb0, pb1;
    // prefetch chunk 0
    pa0 = *(const float4*)(gA);
    pa1 = *(const float4*)(gA + 4);
    pb0 = *(const float4*)(gB);
    pb1 = *(const float4*)(gB + J);

    // convert chunk 0 into stage 0
    {
        char* st = smem;
        float av[8] = {pa0.x, pa0.y, pa0.z, pa0.w, pa1.x, pa1.y, pa1.z, pa1.w};
        uint32_t* ah = (uint32_t*)st;
        uint32_t* al = (uint32_t*)(st + ACV_LO);
#pragma unroll
        for (int jj = 0; jj < 4; jj++) {
            int j = (jj + ra) & 3;
            uint32_t hi, lo;
            split2(av[2 * j], av[2 * j + 1], hi, lo);
            ah[ra * 20 + qa * 4 + j] = hi;
            al[ra * 20 + qa * 4 + j] = lo;
        }
        float bx[4] = {pb0.x, pb0.y, pb0.z, pb0.w};
        float by[4] = {pb1.x, pb1.y, pb1.z, pb1.w};
        uint32_t h[4], l[4];
#pragma unroll
        for (int i2 = 0; i2 < 4; i2++) split2(bx[i2], by[i2], h[i2], l[i2]);
        *(uint4*)(st + BCV_HI + (pk * 136 + n0) * 4) = make_uint4(h[0], h[1], h[2], h[3]);
        *(uint4*)(st + BCV_LO + (pk * 136 + n0) * 4) = make_uint4(l[0], l[1], l[2], l[3]);
    }
    __syncthreads();

#pragma unroll 1
    for (int i = 0; i < 8; i++) {
        // ---- issue register prefetch for chunk i+1 (hidden behind MMA phase)
        if (i < 7) {
            pa0 = *(const float4*)(gA + (i + 1) * 32);
            pa1 = *(const float4*)(gA + (i + 1) * 32 + 4);
            pb0 = *(const float4*)(gB + (size_t)((i + 1) * 32) * J);
            pb1 = *(const float4*)(gB + (size_t)((i + 1) * 32 + 1) * J);
        }

        // ---- MMA phase on stage i&1: pure LDS32 + HMMA
        {
            const char* st = smem + (i & 1) * STG_BYTES;
            const uint32_t* Ah = (const uint32_t*)st;
            const uint32_t* Al = (const uint32_t*)(st + ACV_LO);
            const uint32_t* Bh = (const uint32_t*)(st + BCV_HI);
            const uint32_t* Bl = (const uint32_t*)(st + BCV_LO);
#pragma unroll
            for (int ks = 0; ks < 2; ks++) {
                const int kp0 = ks * 8 + (lane & 3);
                uint32_t ahi[2][4], alo[2][4];
#pragma unroll
                for (int mt = 0; mt < 2; mt++) {
                    int w0 = (wm * 32 + mt * 16 + (lane >> 2)) * 20 + kp0;
                    ahi[mt][0] = Ah[w0];
                    ahi[mt][1] = Ah[w0 + 8 * 20];
                    ahi[mt][2] = Ah[w0 + 4];
                    ahi[mt][3] = Ah[w0 + 8 * 20 + 4];
                    alo[mt][0] = Al[w0];
                    alo[mt][1] = Al[w0 + 8 * 20];
                    alo[mt][2] = Al[w0 + 4];
                    alo[mt][3] = Al[w0 + 8 * 20 + 4];
                }
#pragma unroll
                for (int np = 0; np < 4; np++) {
                    int wb = kp0 * 136 + wn * 32 + np * 8 + (lane >> 2);
                    uint32_t bh[2], bl[2];
                    bh[0] = Bh[wb];
                    bh[1] = Bh[wb + 4 * 136];
                    bl[0] = Bl[wb];
                    bl[1] = Bl[wb + 4 * 136];
#pragma unroll
                    for (int mt = 0; mt < 2; mt++) {
                        mma16816(acc[mt][np], ahi[mt], bh);   // Ahi*Bhi
                        mma16816(acc[mt][np], ahi[mt], bl);   // Ahi*Blo
                        mma16816(acc[mt][np], alo[mt], bh);   // Alo*Bhi
                    }
                }
            }
        }

        // ---- convert chunk i+1 into the other stage (different buffer: no race)
        if (i < 7) {
            char* st = smem + ((i + 1) & 1) * STG_BYTES;
            float av[8] = {pa0.x, pa0.y, pa0.z, pa0.w, pa1.x, pa1.y, pa1.z, pa1.w};
            uint32_t* ah = (uint32_t*)st;
            uint32_t* al = (uint32_t*)(st + ACV_LO);
#pragma unroll
            for (int jj = 0; jj < 4; jj++) {
                int j = (jj + ra) & 3;
                uint32_t hi, lo;
                split2(av[2 * j], av[2 * j + 1], hi, lo);
                ah[ra * 20 + qa * 4 + j] = hi;
                al[ra * 20 + qa * 4 + j] = lo;
            }
            float bx[4] = {pb0.x, pb0.y, pb0.z, pb0.w};
            float by[4] = {pb1.x, pb1.y, pb1.z, pb1.w};
            uint32_t h[4], l[4];
#pragma unroll
            for (int i2 = 0; i2 < 4; i2++) split2(bx[i2], by[i2], h[i2], l[i2]);
            *(uint4*)(st + BCV_HI + (pk * 136 + n0) * 4) = make_uint4(h[0], h[1], h[2], h[3]);
            *(uint4*)(st + BCV_LO + (pk * 136 + n0) * 4) = make_uint4(l[0], l[1], l[2], l[3]);
        }
        __syncthreads();
    }

    // ---- epilogue: (acc + bias) * scale
#pragma unroll
    for (int mt = 0; mt < 2; mt++)
#pragma unroll
        for (int half = 0; half < 2; half++) {
            int o = ot * 128 + wm * 32 + mt * 16 + half * 8 + (lane >> 2);
            float bi = bias[o];
            float* orow = Out + ((size_t)bb * C_DIM + o) * J
                        + (size_t)jt * 128 + wn * 32 + (lane & 3) * 2;
#pragma unroll
            for (int np = 0; np < 4; np++) {
                float2 v;
                v.x = (acc[mt][np][half * 2 + 0] + bi) * scale;
                v.y = (acc[mt][np][half * 2 + 1] + bi) * scale;
                *(float2*)(orow + np * 8) = v;
            }
        }
}

// ------------------------------ attention (unchanged; DRAM/latency-bound)
__global__ __launch_bounds__(256)
void attn_kernel(const float* __restrict__ q, const float* __restrict__ k,
                 const float* __restrict__ v, float* __restrict__ out) {
    int t = blockIdx.x * blockDim.x + threadIdx.x;
    int x = t & 63;
    int y = (t >> 6) & 63;
    int head = (t >> 12) & 7;
    int b = t >> 15;

    const size_t chq = (size_t)(b * C_DIM + head * 32);
    const float* qb = q + chq * HW + y * 64 + x;
    const size_t fbase = chq * HWF + (size_t)(4 * y) * 256 + 4 * x;
    const float* kb = k + fbase;
    const float* vb = v + fbase;

    float logit[16];
#pragma unroll
    for (int p = 0; p < 16; p++) logit[p] = 0.f;

#pragma unroll 4
    for (int d = 0; d < 32; d++) {
        float qd = qb[(size_t)d * HW];
#pragma unroll
        for (int dy = 0; dy < 4; dy++) {
            float4 kv = *(const float4*)(kb + (size_t)d * HWF + dy * 256);
            logit[dy * 4 + 0] = fmaf(qd, kv.x, logit[dy * 4 + 0]);
            logit[dy * 4 + 1] = fmaf(qd, kv.y, logit[dy * 4 + 1]);
            logit[dy * 4 + 2] = fmaf(qd, kv.z, logit[dy * 4 + 2]);
            logit[dy * 4 + 3] = fmaf(qd, kv.w, logit[dy * 4 + 3]);
        }
    }

    float m = logit[0];
#pragma unroll
    for (int p = 1; p < 16; p++) m = fmaxf(m, logit[p]);
    float s = 0.f;
#pragma unroll
    for (int p = 0; p < 16; p++) { logit[p] = __expf(logit[p] - m); s += logit[p]; }
    float inv = 1.f / s;
#pragma unroll
    for (int p = 0; p < 16; p++) logit[p] *= inv;

    float* ob = out + chq * HW + y * 64 + x;
#pragma unroll 4
    for (int d = 0; d < 32; d++) {
        float sum = 0.f;
#pragma unroll
        for (int dy = 0; dy < 4; dy++) {
            float4 vv = *(const float4*)(vb + (size_t)d * HWF + dy * 256);
            sum = fmaf(logit[dy * 4 + 0], vv.x, sum);
            sum = fmaf(logit[dy * 4 + 1], vv.y, sum);
            sum = fmaf(logit[dy * 4 + 2], vv.z, sum);
            sum = fmaf(logit[dy * 4 + 3], vv.w, sum);
        }
        ob[(size_t)d * HW] = sum;
    }
}

// ------------------------------ launch
extern "C" void kernel_launch(void* const* d_in, const int* in_sizes, int n_in,
                              void* d_out, int out_size) {
    const float* x  = (const float*)d_in[0];
    const float* fm = (const float*)d_in[1];
    const float* Wq = (const float*)d_in[2];
    const float* bq = (const float*)d_in[3];
    const float* Wk = (const float*)d_in[4];
    const float* bk = (const float*)d_in[5];
    const float* Wv = (const float*)d_in[6];
    const float* bv = (const float*)d_in[7];
    float* out = (float*)d_out;

    float *q, *k, *v;
    cudaGetSymbolAddress((void**)&q, g_q);
    cudaGetSymbolAddress((void**)&k, g_k);
    cudaGetSymbolAddress((void**)&v, g_v);

    cudaFuncSetAttribute(gemm_mma, cudaFuncAttributeMaxDynamicSharedMemorySize, SMEM_TOT);

    const float scaling = 0.17677669529663687f;  // 32^-0.5

    gemm_mma<<<dim3(HW / 128, 2, 2), 512, SMEM_TOT>>>(Wq, x, bq, q, HW, scaling);
    gemm_mma<<<dim3(HWF / 128, 2, 2), 512, SMEM_TOT>>>(Wk, fm, bk, k, HWF, 1.0f);
    gemm_mma<<<dim3(HWF / 128, 2, 2), 512, SMEM_TOT>>>(Wv, fm, bv, v, HWF, 1.0f);

    attn_kernel<<<(2 * 8 * HW) / 256, 256>>>(q, k, v, out);
}

// round 13
// speedup vs baseline: 1.3000x; 1.2467x over previous
#include <cuda_runtime.h>
#include <cuda_bf16.h>
#include <cuda_fp16.h>
#include <stdint.h>

#define C_DIM 256
#define HW    4096
#define HWF   65536

// ------------------------------ scratch (proven-passing set)
__device__ float g_q[(size_t)2 * C_DIM * HW];
__device__ float g_k[(size_t)2 * C_DIM * HWF];
__device__ float g_v[(size_t)2 * C_DIM * HWF];

// ------------------------------ helpers
__device__ __forceinline__ void mma16816(float* d, const uint32_t* a, const uint32_t* b) {
    asm volatile(
        "mma.sync.aligned.m16n8k16.row.col.f32.f16.f16.f32 "
        "{%0,%1,%2,%3}, {%4,%5,%6,%7}, {%8,%9}, {%0,%1,%2,%3};"
        : "+f"(d[0]), "+f"(d[1]), "+f"(d[2]), "+f"(d[3])
        : "r"(a[0]), "r"(a[1]), "r"(a[2]), "r"(a[3]), "r"(b[0]), "r"(b[1]));
}

// split float pair -> fp16x2 hi (rounded) + fp16x2 lo (residual); f0 in low half
__device__ __forceinline__ void split2h(float f0, float f1, uint32_t& hi, uint32_t& lo) {
    __half2 h2 = __float22half2_rn(make_float2(f0, f1));
    float2 hf = __half22float2(h2);
    __half2 l2 = __float22half2_rn(make_float2(f0 - hf.x, f1 - hf.y));
    hi = *reinterpret_cast<uint32_t*>(&h2);
    lo = *reinterpret_cast<uint32_t*>(&l2);
}
// convert float pair -> fp16x2 (single rounding, no residual)
__device__ __forceinline__ uint32_t cvt2h(float f0, float f1) {
    __half2 h2 = __float22half2_rn(make_float2(f0, f1));
    return *reinterpret_cast<uint32_t*>(&h2);
}

// ------------------------------ warp-MMA GEMM, fp16 2-term split
// Out[bb][ot*128+m][jt*128+n] = (sum_c W[m][c] * F[bb][c][n] + bias[m]) * scale
// A = W as fp16 hi+lo (exact to ~2^-22); B = F as single fp16 (error ~2.8e-4 rms,
// cancels over K=256). 512 threads, 16 warps (4m x 4n), warp tile 32x32,
// CTA tile 128x128, k-chunk 32. Register prefetch -> in-register convert ->
// bf16/fp16 pair-layout smem tiles; MMA phase pure LDS32 + HMMA.
// Per-stage SMEM (29184 B):
//   +0      Acv hi [128m][20 words]  (16 k-pair uint32 + 4 pad)
//   +10240  Acv lo [128m][20 words]
//   +20480  Bcv    [16kp][136 words] (128 n + 8 pad)
#define ACV_LO   10240
#define BCV_HI   20480
#define STG_BYTES 29184
#define SMEM_TOT (2 * STG_BYTES)    // 58368

__global__ __launch_bounds__(512, 1)
void gemm_mma(const float* __restrict__ W, const float* __restrict__ F,
              const float* __restrict__ bias, float* __restrict__ Out,
              int J, float scale) {
    extern __shared__ char smem[];
    const int t = threadIdx.x, lane = t & 31;
    const int wid = t >> 5, wm = wid & 3, wn = wid >> 2;
    const int jt = blockIdx.x, ot = blockIdx.y, bb = blockIdx.z;

    // prefetch coordinates
    const int ra = t >> 2, qa = t & 3;         // A: row 0..127, k-segment of 8
    const int pk = t >> 5, n0 = (t & 31) * 4;  // B: k-pair row 0..15, 4 n-cols
    const float* gA = W + (size_t)(ot * 128 + ra) * C_DIM + qa * 8;
    const float* gB = F + (size_t)bb * C_DIM * J + (size_t)(2 * pk) * J
                    + (size_t)jt * 128 + n0;

    float acc[2][4][4];
#pragma unroll
    for (int mt = 0; mt < 2; mt++)
#pragma unroll
        for (int np = 0; np < 4; np++)
#pragma unroll
            for (int r = 0; r < 4; r++) acc[mt][np][r] = 0.f;

    float4 pa0, pa1, pb0, pb1;
    // prefetch chunk 0
    pa0 = *(const float4*)(gA);
    pa1 = *(const float4*)(gA + 4);
    pb0 = *(const float4*)(gB);
    pb1 = *(const float4*)(gB + J);

    // convert chunk 0 into stage 0
    {
        char* st = smem;
        float av[8] = {pa0.x, pa0.y, pa0.z, pa0.w, pa1.x, pa1.y, pa1.z, pa1.w};
        uint32_t* ah = (uint32_t*)st;
        uint32_t* al = (uint32_t*)(st + ACV_LO);
#pragma unroll
        for (int jj = 0; jj < 4; jj++) {
            int j = (jj + ra) & 3;
            uint32_t hi, lo;
            split2h(av[2 * j], av[2 * j + 1], hi, lo);
            ah[ra * 20 + qa * 4 + j] = hi;
            al[ra * 20 + qa * 4 + j] = lo;
        }
        uint32_t h[4];
        h[0] = cvt2h(pb0.x, pb1.x);
        h[1] = cvt2h(pb0.y, pb1.y);
        h[2] = cvt2h(pb0.z, pb1.z);
        h[3] = cvt2h(pb0.w, pb1.w);
        *(uint4*)(st + BCV_HI + (pk * 136 + n0) * 4) = make_uint4(h[0], h[1], h[2], h[3]);
    }
    __syncthreads();

#pragma unroll 1
    for (int i = 0; i < 8; i++) {
        // ---- issue register prefetch for chunk i+1 (hidden behind MMA phase)
        if (i < 7) {
            pa0 = *(const float4*)(gA + (i + 1) * 32);
            pa1 = *(const float4*)(gA + (i + 1) * 32 + 4);
            pb0 = *(const float4*)(gB + (size_t)((i + 1) * 32) * J);
            pb1 = *(const float4*)(gB + (size_t)((i + 1) * 32 + 1) * J);
        }

        // ---- MMA phase on stage i&1: pure LDS32 + HMMA (2 terms)
        {
            const char* st = smem + (i & 1) * STG_BYTES;
            const uint32_t* Ah = (const uint32_t*)st;
            const uint32_t* Al = (const uint32_t*)(st + ACV_LO);
            const uint32_t* Bh = (const uint32_t*)(st + BCV_HI);
#pragma unroll
            for (int ks = 0; ks < 2; ks++) {
                const int kp0 = ks * 8 + (lane & 3);
                uint32_t ahi[2][4], alo[2][4];
#pragma unroll
                for (int mt = 0; mt < 2; mt++) {
                    int w0 = (wm * 32 + mt * 16 + (lane >> 2)) * 20 + kp0;
                    ahi[mt][0] = Ah[w0];
                    ahi[mt][1] = Ah[w0 + 8 * 20];
                    ahi[mt][2] = Ah[w0 + 4];
                    ahi[mt][3] = Ah[w0 + 8 * 20 + 4];
                    alo[mt][0] = Al[w0];
                    alo[mt][1] = Al[w0 + 8 * 20];
                    alo[mt][2] = Al[w0 + 4];
                    alo[mt][3] = Al[w0 + 8 * 20 + 4];
                }
#pragma unroll
                for (int np = 0; np < 4; np++) {
                    int wb = kp0 * 136 + wn * 32 + np * 8 + (lane >> 2);
                    uint32_t bh[2];
                    bh[0] = Bh[wb];
                    bh[1] = Bh[wb + 4 * 136];
#pragma unroll
                    for (int mt = 0; mt < 2; mt++) {
                        mma16816(acc[mt][np], ahi[mt], bh);   // Ahi*B
                        mma16816(acc[mt][np], alo[mt], bh);   // Alo*B
                    }
                }
            }
        }

        // ---- convert chunk i+1 into the other stage (different buffer: no race)
        if (i < 7) {
            char* st = smem + ((i + 1) & 1) * STG_BYTES;
            float av[8] = {pa0.x, pa0.y, pa0.z, pa0.w, pa1.x, pa1.y, pa1.z, pa1.w};
            uint32_t* ah = (uint32_t*)st;
            uint32_t* al = (uint32_t*)(st + ACV_LO);
#pragma unroll
            for (int jj = 0; jj < 4; jj++) {
                int j = (jj + ra) & 3;
                uint32_t hi, lo;
                split2h(av[2 * j], av[2 * j + 1], hi, lo);
                ah[ra * 20 + qa * 4 + j] = hi;
                al[ra * 20 + qa * 4 + j] = lo;
            }
            uint32_t h[4];
            h[0] = cvt2h(pb0.x, pb1.x);
            h[1] = cvt2h(pb0.y, pb1.y);
            h[2] = cvt2h(pb0.z, pb1.z);
            h[3] = cvt2h(pb0.w, pb1.w);
            *(uint4*)(st + BCV_HI + (pk * 136 + n0) * 4) = make_uint4(h[0], h[1], h[2], h[3]);
        }
        __syncthreads();
    }

    // ---- epilogue: (acc + bias) * scale
#pragma unroll
    for (int mt = 0; mt < 2; mt++)
#pragma unroll
        for (int half = 0; half < 2; half++) {
            int o = ot * 128 + wm * 32 + mt * 16 + half * 8 + (lane >> 2);
            float bi = bias[o];
            float* orow = Out + ((size_t)bb * C_DIM + o) * J
                        + (size_t)jt * 128 + wn * 32 + (lane & 3) * 2;
#pragma unroll
            for (int np = 0; np < 4; np++) {
                float2 v;
                v.x = (acc[mt][np][half * 2 + 0] + bi) * scale;
                v.y = (acc[mt][np][half * 2 + 1] + bi) * scale;
                *(float2*)(orow + np * 8) = v;
            }
        }
}

// ------------------------------ attention, 4 threads per query
// sub-lane (t&3) owns 8 of 32 head-dims; logits butterfly-reduced over lanes
// differing in bits 0..1 (same query), softmax redundant, V gather partial.
__global__ __launch_bounds__(256)
void attn_kernel(const float* __restrict__ q, const float* __restrict__ k,
                 const float* __restrict__ v, float* __restrict__ out) {
    int t = blockIdx.x * blockDim.x + threadIdx.x;   // 262144 threads
    int sub = t & 3;
    int qid = t >> 2;                                // 0..65535
    int x = qid & 63;
    int y = (qid >> 6) & 63;
    int head = (qid >> 12) & 7;
    int b = qid >> 15;

    const size_t chq = (size_t)(b * C_DIM + head * 32) + sub * 8;
    const float* qb = q + chq * HW + y * 64 + x;
    const size_t fbase = chq * HWF + (size_t)(4 * y) * 256 + 4 * x;
    const float* kb = k + fbase;
    const float* vb = v + fbase;

    float logit[16];
#pragma unroll
    for (int p = 0; p < 16; p++) logit[p] = 0.f;

#pragma unroll
    for (int dd = 0; dd < 8; dd++) {
        float qd = qb[(size_t)dd * HW];
#pragma unroll
        for (int dy = 0; dy < 4; dy++) {
            float4 kv = *(const float4*)(kb + (size_t)dd * HWF + dy * 256);
            logit[dy * 4 + 0] = fmaf(qd, kv.x, logit[dy * 4 + 0]);
            logit[dy * 4 + 1] = fmaf(qd, kv.y, logit[dy * 4 + 1]);
            logit[dy * 4 + 2] = fmaf(qd, kv.z, logit[dy * 4 + 2]);
            logit[dy * 4 + 3] = fmaf(qd, kv.w, logit[dy * 4 + 3]);
        }
    }

    // reduce partial logits across the 4 sub-lanes of this query
#pragma unroll
    for (int p = 0; p < 16; p++) {
        logit[p] += __shfl_xor_sync(0xFFFFFFFFu, logit[p], 1);
        logit[p] += __shfl_xor_sync(0xFFFFFFFFu, logit[p], 2);
    }

    float m = logit[0];
#pragma unroll
    for (int p = 1; p < 16; p++) m = fmaxf(m, logit[p]);
    float s = 0.f;
#pragma unroll
    for (int p = 0; p < 16; p++) { logit[p] = __expf(logit[p] - m); s += logit[p]; }
    float inv = 1.f / s;
#pragma unroll
    for (int p = 0; p < 16; p++) logit[p] *= inv;

    float* ob = out + chq * HW + y * 64 + x;
#pragma unroll
    for (int dd = 0; dd < 8; dd++) {
        float sum = 0.f;
#pragma unroll
        for (int dy = 0; dy < 4; dy++) {
            float4 vv = *(const float4*)(vb + (size_t)dd * HWF + dy * 256);
            sum = fmaf(logit[dy * 4 + 0], vv.x, sum);
            sum = fmaf(logit[dy * 4 + 1], vv.y, sum);
            sum = fmaf(logit[dy * 4 + 2], vv.z, sum);
            sum = fmaf(logit[dy * 4 + 3], vv.w, sum);
        }
        ob[(size_t)dd * HW] = sum;
    }
}

// ------------------------------ launch
extern "C" void kernel_launch(void* const* d_in, const int* in_sizes, int n_in,
                              void* d_out, int out_size) {
    const float* x  = (const float*)d_in[0];
    const float* fm = (const float*)d_in[1];
    const float* Wq = (const float*)d_in[2];
    const float* bq = (const float*)d_in[3];
    const float* Wk = (const float*)d_in[4];
    const float* bk = (const float*)d_in[5];
    const float* Wv = (const float*)d_in[6];
    const float* bv = (const float*)d_in[7];
    float* out = (float*)d_out;

    float *q, *k, *v;
    cudaGetSymbolAddress((void**)&q, g_q);
    cudaGetSymbolAddress((void**)&k, g_k);
    cudaGetSymbolAddress((void**)&v, g_v);

    cudaFuncSetAttribute(gemm_mma, cudaFuncAttributeMaxDynamicSharedMemorySize, SMEM_TOT);

    const float scaling = 0.17677669529663687f;  // 32^-0.5

    gemm_mma<<<dim3(HW / 128, 2, 2), 512, SMEM_TOT>>>(Wq, x, bq, q, HW, scaling);
    gemm_mma<<<dim3(HWF / 128, 2, 2), 512, SMEM_TOT>>>(Wk, fm, bk, k, HWF, 1.0f);
    gemm_mma<<<dim3(HWF / 128, 2, 2), 512, SMEM_TOT>>>(Wv, fm, bv, v, HWF, 1.0f);

    attn_kernel<<<(2 * 8 * HW * 4) / 256, 256>>>(q, k, v, out);
}